// round 10
// baseline (speedup 1.0000x reference)
#include <cuda_runtime.h>
#include <cuda_fp16.h>
#include <math.h>
#include <stdint.h>

#define DIM 64
#define TM 128
#define TN 128
#define NJ 4     // column tiles processed per CTA

// ---------------------------------------------------------------------------
// helpers
// ---------------------------------------------------------------------------
__device__ __forceinline__ uint32_t packh2(float lo, float hi) {
    __half2 h = __floats2half2_rn(lo, hi);
    return *reinterpret_cast<uint32_t*>(&h);
}

__device__ __forceinline__ float sqrt_approx(float v) {
    float r;
    asm("sqrt.approx.f32 %0, %1;" : "=f"(r) : "f"(v));
    return r;
}

__device__ __forceinline__ float dist_val(float s, float a) {
    return sqrt_approx(fmaxf(fmaf(-2.0f, a, s), 1e-12f));
}

__device__ __forceinline__ void mma_f16(float c[4], const uint32_t a[4],
                                        const uint32_t b0, const uint32_t b1) {
    asm volatile(
        "mma.sync.aligned.m16n8k16.row.col.f32.f16.f16.f32 "
        "{%0,%1,%2,%3}, {%4,%5,%6,%7}, {%8,%9}, {%0,%1,%2,%3};"
        : "+f"(c[0]), "+f"(c[1]), "+f"(c[2]), "+f"(c[3])
        : "r"(a[0]), "r"(a[1]), "r"(a[2]), "r"(a[3]), "r"(b0), "r"(b1));
}

__device__ __forceinline__ void ldsm_x4(uint32_t& r0, uint32_t& r1,
                                        uint32_t& r2, uint32_t& r3,
                                        uint32_t addr) {
    asm volatile("ldmatrix.sync.aligned.m8n8.x4.shared.b16 {%0,%1,%2,%3}, [%4];"
                 : "=r"(r0), "=r"(r1), "=r"(r2), "=r"(r3) : "r"(addr));
}

// ---------------------------------------------------------------------------
// Single fused kernel: norms + fp16 mma GEMM + sqrt epilogue.
// CTA: 128-row strip x NJ*128 columns; A tile + x2 filled ONCE, then NJ
// sub-tiles of B processed in a loop (B fill -> mma -> epilogue).
// Tiles SW128-swizzled, 128B rows. B columns PERMUTED (per 16-col group:
// physical p=4t+s -> tile s>=2, col 2t+(s&1)) so each thread's epilogue quad
// is 4 contiguous output columns -> STG.128.
//   out[b,j] = sqrt(max(x2[b] + w2[j] - 2*dot, 1e-12))
// ---------------------------------------------------------------------------
__global__ __launch_bounds__(256, 2) void dist_mma_kernel(
    const float* __restrict__ x, const float* __restrict__ w,
    float* __restrict__ out, int B, int K)
{
    __shared__ uint32_t As[128 * 32];   // A[m][k] f16 pairs, SW128
    __shared__ uint32_t Bs[128 * 32];   // B[L][k] f16 pairs, SW128, permuted cols
    __shared__ float x2s[128];
    __shared__ float w2p[2][128];       // w2 partials per k-half, physical col

    const int tid = threadIdx.x;
    const int lane = tid & 31;
    const int wid = tid >> 5;
    const int warp_m = wid >> 2;      // 0..1
    const int warp_n = wid & 3;       // 0..3
    const int m0 = blockIdx.y * TM;

    // ---- A tile fill (once per CTA) + inline x2 via shuffle reduction ----
    {
        const float4* xs = reinterpret_cast<const float4*>(x + (long)m0 * DIM);
#pragma unroll
        for (int i = 0; i < 8; i++) {
            int e = tid + i * 256;       // float4 index, 0..2047
            int r = e >> 4;              // 16 float4 per 64-float row
            int c4 = e & 15;             // == lane & 15
            float4 v = xs[e];
            float s = v.x * v.x + v.y * v.y + v.z * v.z + v.w * v.w;
            s += __shfl_xor_sync(0xffffffffu, s, 1);
            s += __shfl_xor_sync(0xffffffffu, s, 2);
            s += __shfl_xor_sync(0xffffffffu, s, 4);
            s += __shfl_xor_sync(0xffffffffu, s, 8);
            if (c4 == 0) x2s[r] = s;
            int word = r * 32 + ((c4 * 2) ^ ((r & 7) << 2));
            *reinterpret_cast<uint2*>(&As[word]) =
                make_uint2(packh2(v.x, v.y), packh2(v.z, v.w));
        }
    }

    // ---- constants for B fill ----
    const int nB = tid & 127;          // physical column within tile
    const int khalf = tid >> 7;        // k base 0 / 32
    const int grpB = nB >> 4, pB = nB & 15;
    const int tqB = pB >> 2, s4B = pB & 3;
    const int LB = grpB * 16 + (s4B >> 1) * 8 + tqB * 2 + (s4B & 1);

    // ---- constants for mainloop ----
    const int g = lane >> 2;
    const int t = lane & 3;
    uint32_t As_base = (uint32_t)__cvta_generic_to_shared(As);
    uint32_t Bs_base = (uint32_t)__cvta_generic_to_shared(Bs);
    const int rowA_loc = lane & 15;
    const int a_klo = lane >> 4;
    const int sxA = rowA_loc & 7;
    const int rowB_loc = (lane & 7) + ((lane >> 4) << 3);
    const int b_klo = (lane >> 3) & 1;
    const int sxB = rowB_loc & 7;
    const uint32_t baseA = As_base + (uint32_t)((warp_m * 64 + rowA_loc) << 7);
    const uint32_t baseB0 = Bs_base + (uint32_t)((warp_n * 32 + rowB_loc) << 7);
    const uint32_t baseB1 = baseB0 + (16 << 7);

    for (int jt = 0; jt < NJ; jt++) {
        const int j0 = (blockIdx.x * NJ + jt) * TN;
        if (j0 >= K) break;

        // barrier: A-fill complete (iter 0) / prior epilogue w2p reads done
        __syncthreads();

        // ---- B tile fill (transposed, permuted, swizzled) + w2 partials ----
        {
            int j = j0 + nB;
            bool inb = (j < K);
            const float* wp = w + j;
            float s = 0.0f;
#pragma unroll
            for (int q = 0; q < 4; q++) {
                float f[8];
#pragma unroll
                for (int dd = 0; dd < 8; dd++) {
                    int d = khalf * 32 + q * 8 + dd;
                    f[dd] = inb ? wp[(long)d * K] : 0.0f;
                    s += f[dd] * f[dd];
                }
                uint4 u = make_uint4(packh2(f[0], f[1]), packh2(f[2], f[3]),
                                     packh2(f[4], f[5]), packh2(f[6], f[7]));
                int word = LB * 32 + (((khalf * 4 + q) ^ (LB & 7)) << 2);
                *reinterpret_cast<uint4*>(&Bs[word]) = u;
            }
            w2p[khalf][nB] = s;
        }

        __syncthreads();

        // ---- MMA mainloop: 4 k-steps; A fragment loaded per-mt ----
        float acc[4][4][4];
#pragma unroll
        for (int mt = 0; mt < 4; mt++)
#pragma unroll
            for (int nt = 0; nt < 4; nt++)
#pragma unroll
                for (int q = 0; q < 4; q++) acc[mt][nt][q] = 0.0f;

#pragma unroll
        for (int ks = 0; ks < 4; ks++) {
            uint32_t colA = (uint32_t)(((2 * ks + a_klo) ^ sxA) << 4);
            uint32_t colB = (uint32_t)(((2 * ks + b_klo) ^ sxB) << 4);

            uint32_t b0[4], b1[4];
            ldsm_x4(b0[0], b0[1], b0[2], b0[3], baseB0 + colB);
            ldsm_x4(b1[0], b1[1], b1[2], b1[3], baseB1 + colB);

#pragma unroll
            for (int mt = 0; mt < 4; mt++) {
                uint32_t a[4];
                ldsm_x4(a[0], a[1], a[2], a[3],
                        baseA + (uint32_t)(mt << 11) + colA);
                mma_f16(acc[mt][0], a, b0[0], b0[1]);
                mma_f16(acc[mt][1], a, b0[2], b0[3]);
                mma_f16(acc[mt][2], a, b1[0], b1[1]);
                mma_f16(acc[mt][3], a, b1[2], b1[3]);
            }
        }

        // ---- Epilogue ----
        float w2v[2][4];
#pragma unroll
        for (int ntp = 0; ntp < 2; ntp++)
#pragma unroll
            for (int q = 0; q < 4; q++) {
                int col = warp_n * 32 + ntp * 16 + 4 * t + q;
                w2v[ntp][q] = w2p[0][col] + w2p[1][col];
            }

        const int jbase = j0 + warp_n * 32 + 4 * t;

        if (j0 + TN <= K) {
#pragma unroll
            for (int mt = 0; mt < 4; mt++) {
                int R = warp_m * 64 + mt * 16 + g;
                float x2lo = x2s[R];
                float x2hi = x2s[R + 8];
                float* o0 = out + (long)(m0 + R) * K + jbase;
                float* o1 = out + (long)(m0 + R + 8) * K + jbase;
#pragma unroll
                for (int ntp = 0; ntp < 2; ntp++) {
                    const float* aq0 = acc[mt][2 * ntp + 0];
                    const float* aq1 = acc[mt][2 * ntp + 1];
                    float4 lo, hi;
                    lo.x = dist_val(x2lo + w2v[ntp][0], aq0[0]);
                    lo.y = dist_val(x2lo + w2v[ntp][1], aq0[1]);
                    lo.z = dist_val(x2lo + w2v[ntp][2], aq1[0]);
                    lo.w = dist_val(x2lo + w2v[ntp][3], aq1[1]);
                    hi.x = dist_val(x2hi + w2v[ntp][0], aq0[2]);
                    hi.y = dist_val(x2hi + w2v[ntp][1], aq0[3]);
                    hi.z = dist_val(x2hi + w2v[ntp][2], aq1[2]);
                    hi.w = dist_val(x2hi + w2v[ntp][3], aq1[3]);
                    *reinterpret_cast<float4*>(o0 + ntp * 16) = lo;
                    *reinterpret_cast<float4*>(o1 + ntp * 16) = hi;
                }
            }
        } else {
#pragma unroll
            for (int mt = 0; mt < 4; mt++) {
                int R = warp_m * 64 + mt * 16 + g;
                float x2lo = x2s[R];
                float x2hi = x2s[R + 8];
                long row0 = (long)(m0 + R) * K;
                long row1 = (long)(m0 + R + 8) * K;
                for (int ntp = 0; ntp < 2; ntp++) {
                    const float* aq0 = acc[mt][2 * ntp + 0];
                    const float* aq1 = acc[mt][2 * ntp + 1];
                    for (int q = 0; q < 4; q++) {
                        int j = jbase + ntp * 16 + q;
                        if (j >= K) continue;
                        float a0 = (q < 2) ? aq0[q] : aq1[q - 2];
                        float a1 = (q < 2) ? aq0[q + 2] : aq1[q];
                        out[row0 + j] = dist_val(x2lo + w2v[ntp][q], a0);
                        out[row1 + j] = dist_val(x2hi + w2v[ntp][q], a1);
                    }
                }
            }
        }
    }
}

// ---------------------------------------------------------------------------
// Launch (single kernel)
// ---------------------------------------------------------------------------
extern "C" void kernel_launch(void* const* d_in, const int* in_sizes, int n_in,
                              void* d_out, int out_size) {
    const float* x = (const float*)d_in[0];   // [B, 64]
    const float* w = (const float*)d_in[1];   // [64, K]
    float* out = (float*)d_out;               // [B, K]

    int B = in_sizes[0] / DIM;
    int K = in_sizes[1] / DIM;

    dim3 grid((K + TN * NJ - 1) / (TN * NJ), (B + TM - 1) / TM);
    dist_mma_kernel<<<grid, 256>>>(x, w, out, B, K);
}

// round 11
// speedup vs baseline: 1.0306x; 1.0306x over previous
#include <cuda_runtime.h>
#include <cuda_fp16.h>
#include <math.h>
#include <stdint.h>

#define DIM 64
#define TM 128
#define TN 256
#define NTHREADS 512

// ---------------------------------------------------------------------------
// helpers
// ---------------------------------------------------------------------------
__device__ __forceinline__ uint32_t packh2(float lo, float hi) {
    __half2 h = __floats2half2_rn(lo, hi);
    return *reinterpret_cast<uint32_t*>(&h);
}

__device__ __forceinline__ float sqrt_approx(float v) {
    float r;
    asm("sqrt.approx.f32 %0, %1;" : "=f"(r) : "f"(v));
    return r;
}

__device__ __forceinline__ float dist_val(float s, float a) {
    return sqrt_approx(fmaxf(fmaf(-2.0f, a, s), 1e-12f));
}

__device__ __forceinline__ void mma_f16(float c[4], const uint32_t a[4],
                                        const uint32_t b0, const uint32_t b1) {
    asm volatile(
        "mma.sync.aligned.m16n8k16.row.col.f32.f16.f16.f32 "
        "{%0,%1,%2,%3}, {%4,%5,%6,%7}, {%8,%9}, {%0,%1,%2,%3};"
        : "+f"(c[0]), "+f"(c[1]), "+f"(c[2]), "+f"(c[3])
        : "r"(a[0]), "r"(a[1]), "r"(a[2]), "r"(a[3]), "r"(b0), "r"(b1));
}

__device__ __forceinline__ void ldsm_x4(uint32_t& r0, uint32_t& r1,
                                        uint32_t& r2, uint32_t& r3,
                                        uint32_t addr) {
    asm volatile("ldmatrix.sync.aligned.m8n8.x4.shared.b16 {%0,%1,%2,%3}, [%4];"
                 : "=r"(r0), "=r"(r1), "=r"(r2), "=r"(r3) : "r"(addr));
}

// ---------------------------------------------------------------------------
// Single fused kernel: norms + fp16 mma GEMM + sqrt epilogue.
// CTA: 128x256 tile, 512 threads = 16 warps (2m x 8n), warp tile 64x32.
// Tiles SW128-swizzled, 128B rows. B columns PERMUTED (per 16-col group:
// physical p=4t+s -> tile s>=2, col 2t+(s&1)) so each thread's epilogue quad
// is 4 contiguous output columns -> STG.128.
//   out[b,j] = sqrt(max(x2[b] + w2[j] - 2*dot, 1e-12))
// Dynamic smem layout (bytes):
//   As   [128*32 u32]  @ 0       (16 KB)
//   Bs   [256*32 u32]  @ 16384   (32 KB)
//   x2s  [128 f32]     @ 49152   (512 B)
//   w2p  [2][256] f32  @ 49664   (2 KB)     total 51712 B
// ---------------------------------------------------------------------------
#define SM_AS   0
#define SM_BS   16384
#define SM_X2   49152
#define SM_W2P  49664
#define SM_TOTAL 51712

__global__ __launch_bounds__(NTHREADS, 1) void dist_mma_kernel(
    const float* __restrict__ x, const float* __restrict__ w,
    float* __restrict__ out, int B, int K)
{
    extern __shared__ char smem[];
    uint32_t* As = reinterpret_cast<uint32_t*>(smem + SM_AS);
    uint32_t* Bs = reinterpret_cast<uint32_t*>(smem + SM_BS);
    float* x2s = reinterpret_cast<float*>(smem + SM_X2);
    float* w2p0 = reinterpret_cast<float*>(smem + SM_W2P);
    float* w2p1 = w2p0 + 256;

    const int tid = threadIdx.x;
    const int lane = tid & 31;
    const int wid = tid >> 5;
    const int warp_m = wid >> 3;      // 0..1
    const int warp_n = wid & 7;       // 0..7
    const int m0 = blockIdx.y * TM;
    const int j0 = blockIdx.x * TN;
    const bool full = (j0 + TN <= K);

    // ---- A tile fill (coalesced) + inline x2 via shuffle reduction ----
    {
        const float4* xs = reinterpret_cast<const float4*>(x + (long)m0 * DIM);
#pragma unroll
        for (int i = 0; i < 4; i++) {
            int e = tid + i * NTHREADS;  // float4 index, 0..2047
            int r = e >> 4;              // 16 float4 per 64-float row
            int c4 = e & 15;             // == lane & 15
            float4 v = xs[e];
            float s = v.x * v.x + v.y * v.y + v.z * v.z + v.w * v.w;
            s += __shfl_xor_sync(0xffffffffu, s, 1);
            s += __shfl_xor_sync(0xffffffffu, s, 2);
            s += __shfl_xor_sync(0xffffffffu, s, 4);
            s += __shfl_xor_sync(0xffffffffu, s, 8);
            if (c4 == 0) x2s[r] = s;
            int word = r * 32 + ((c4 * 2) ^ ((r & 7) << 2));
            *reinterpret_cast<uint2*>(&As[word]) =
                make_uint2(packh2(v.x, v.y), packh2(v.z, v.w));
        }
    }

    // ---- B tile fill (transposed, permuted, swizzled) + w2 partials ----
    {
        int n = tid & 255;            // physical column within tile
        int khalf = tid >> 8;         // k base 0 / 32
        int grp = n >> 4, p = n & 15;
        int tq = p >> 2, s4 = p & 3;
        int L = grp * 16 + (s4 >> 1) * 8 + tq * 2 + (s4 & 1);   // storage row

        const float* wp = w + (j0 + n);
        float s = 0.0f;
        if (full) {
#pragma unroll
            for (int q = 0; q < 4; q++) {
                float f[8];
#pragma unroll
                for (int dd = 0; dd < 8; dd++) {
                    int d = khalf * 32 + q * 8 + dd;
                    f[dd] = wp[(long)d * K];
                    s += f[dd] * f[dd];
                }
                uint4 u = make_uint4(packh2(f[0], f[1]), packh2(f[2], f[3]),
                                     packh2(f[4], f[5]), packh2(f[6], f[7]));
                int word = L * 32 + (((khalf * 4 + q) ^ (L & 7)) << 2);
                *reinterpret_cast<uint4*>(&Bs[word]) = u;
            }
        } else {
            bool inb = (j0 + n < K);
#pragma unroll
            for (int q = 0; q < 4; q++) {
                float f[8];
#pragma unroll
                for (int dd = 0; dd < 8; dd++) {
                    int d = khalf * 32 + q * 8 + dd;
                    f[dd] = inb ? wp[(long)d * K] : 0.0f;
                    s += f[dd] * f[dd];
                }
                uint4 u = make_uint4(packh2(f[0], f[1]), packh2(f[2], f[3]),
                                     packh2(f[4], f[5]), packh2(f[6], f[7]));
                int word = L * 32 + (((khalf * 4 + q) ^ (L & 7)) << 2);
                *reinterpret_cast<uint4*>(&Bs[word]) = u;
            }
        }
        if (khalf == 0) w2p0[n] = s; else w2p1[n] = s;
    }

    __syncthreads();

    // ---- MMA mainloop: 4 k-steps; A fragment loaded per-mt ----
    float acc[4][4][4];
#pragma unroll
    for (int mt = 0; mt < 4; mt++)
#pragma unroll
        for (int nt = 0; nt < 4; nt++)
#pragma unroll
            for (int q = 0; q < 4; q++) acc[mt][nt][q] = 0.0f;

    const int g = lane >> 2;
    const int t = lane & 3;

    uint32_t As_base = (uint32_t)__cvta_generic_to_shared(As);
    uint32_t Bs_base = (uint32_t)__cvta_generic_to_shared(Bs);

    const int rowA_loc = lane & 15;
    const int a_klo = lane >> 4;
    const int sxA = rowA_loc & 7;
    const int rowB_loc = (lane & 7) + ((lane >> 4) << 3);
    const int b_klo = (lane >> 3) & 1;
    const int sxB = rowB_loc & 7;

    const uint32_t baseA = As_base + (uint32_t)((warp_m * 64 + rowA_loc) << 7);
    const uint32_t baseB0 = Bs_base + (uint32_t)((warp_n * 32 + rowB_loc) << 7);
    const uint32_t baseB1 = baseB0 + (16 << 7);

#pragma unroll
    for (int ks = 0; ks < 4; ks++) {
        uint32_t colA = (uint32_t)(((2 * ks + a_klo) ^ sxA) << 4);
        uint32_t colB = (uint32_t)(((2 * ks + b_klo) ^ sxB) << 4);

        uint32_t b0[4], b1[4];
        ldsm_x4(b0[0], b0[1], b0[2], b0[3], baseB0 + colB);
        ldsm_x4(b1[0], b1[1], b1[2], b1[3], baseB1 + colB);

#pragma unroll
        for (int mt = 0; mt < 4; mt++) {
            uint32_t a[4];
            ldsm_x4(a[0], a[1], a[2], a[3], baseA + (uint32_t)(mt << 11) + colA);
            mma_f16(acc[mt][0], a, b0[0], b0[1]);
            mma_f16(acc[mt][1], a, b0[2], b0[3]);
            mma_f16(acc[mt][2], a, b1[0], b1[1]);
            mma_f16(acc[mt][3], a, b1[2], b1[3]);
        }
    }

    // ---- Epilogue ----
    float w2v[2][4];
#pragma unroll
    for (int ntp = 0; ntp < 2; ntp++)
#pragma unroll
        for (int q = 0; q < 4; q++) {
            int col = warp_n * 32 + ntp * 16 + 4 * t + q;
            w2v[ntp][q] = w2p0[col] + w2p1[col];
        }

    const int jbase = j0 + warp_n * 32 + 4 * t;

    if (full) {
#pragma unroll
        for (int mt = 0; mt < 4; mt++) {
            int R = warp_m * 64 + mt * 16 + g;
            float x2lo = x2s[R];
            float x2hi = x2s[R + 8];
            float* o0 = out + (long)(m0 + R) * K + jbase;
            float* o1 = out + (long)(m0 + R + 8) * K + jbase;
#pragma unroll
            for (int ntp = 0; ntp < 2; ntp++) {
                const float* aq0 = acc[mt][2 * ntp + 0];
                const float* aq1 = acc[mt][2 * ntp + 1];
                float4 lo, hi;
                lo.x = dist_val(x2lo + w2v[ntp][0], aq0[0]);
                lo.y = dist_val(x2lo + w2v[ntp][1], aq0[1]);
                lo.z = dist_val(x2lo + w2v[ntp][2], aq1[0]);
                lo.w = dist_val(x2lo + w2v[ntp][3], aq1[1]);
                hi.x = dist_val(x2hi + w2v[ntp][0], aq0[2]);
                hi.y = dist_val(x2hi + w2v[ntp][1], aq0[3]);
                hi.z = dist_val(x2hi + w2v[ntp][2], aq1[2]);
                hi.w = dist_val(x2hi + w2v[ntp][3], aq1[3]);
                *reinterpret_cast<float4*>(o0 + ntp * 16) = lo;
                *reinterpret_cast<float4*>(o1 + ntp * 16) = hi;
            }
        }
    } else {
#pragma unroll
        for (int mt = 0; mt < 4; mt++) {
            int R = warp_m * 64 + mt * 16 + g;
            float x2lo = x2s[R];
            float x2hi = x2s[R + 8];
            long row0 = (long)(m0 + R) * K;
            long row1 = (long)(m0 + R + 8) * K;
            for (int ntp = 0; ntp < 2; ntp++) {
                const float* aq0 = acc[mt][2 * ntp + 0];
                const float* aq1 = acc[mt][2 * ntp + 1];
                for (int q = 0; q < 4; q++) {
                    int j = jbase + ntp * 16 + q;
                    if (j >= K) continue;
                    float a0 = (q < 2) ? aq0[q] : aq1[q - 2];
                    float a1 = (q < 2) ? aq0[q + 2] : aq1[q];
                    out[row0 + j] = dist_val(x2lo + w2v[ntp][q], a0);
                    out[row1 + j] = dist_val(x2hi + w2v[ntp][q], a1);
                }
            }
        }
    }
}

// ---------------------------------------------------------------------------
// Launch (single kernel)
// ---------------------------------------------------------------------------
extern "C" void kernel_launch(void* const* d_in, const int* in_sizes, int n_in,
                              void* d_out, int out_size) {
    const float* x = (const float*)d_in[0];   // [B, 64]
    const float* w = (const float*)d_in[1];   // [64, K]
    float* out = (float*)d_out;               // [B, K]

    int B = in_sizes[0] / DIM;
    int K = in_sizes[1] / DIM;

    cudaFuncSetAttribute(dist_mma_kernel,
                         cudaFuncAttributeMaxDynamicSharedMemorySize, SM_TOTAL);
    dim3 grid((K + TN - 1) / TN, (B + TM - 1) / TM);
    dist_mma_kernel<<<grid, NTHREADS, SM_TOTAL>>>(x, w, out, B, K);
}

// round 12
// speedup vs baseline: 1.0729x; 1.0411x over previous
#include <cuda_runtime.h>
#include <cuda_fp16.h>
#include <math.h>
#include <stdint.h>

#define DIM 64
#define TM 128
#define TN 128
#define NTHREADS 256
#define NCHUNK 24   // column-tile chunks per m-strip

// ---------------------------------------------------------------------------
// helpers
// ---------------------------------------------------------------------------
__device__ __forceinline__ uint32_t packh2(float lo, float hi) {
    __half2 h = __floats2half2_rn(lo, hi);
    return *reinterpret_cast<uint32_t*>(&h);
}

__device__ __forceinline__ float sqrt_approx(float v) {
    float r;
    asm("sqrt.approx.f32 %0, %1;" : "=f"(r) : "f"(v));
    return r;
}

__device__ __forceinline__ float dist_val(float s, float a) {
    return sqrt_approx(fmaxf(fmaf(-2.0f, a, s), 1e-12f));
}

__device__ __forceinline__ void mma_f16(float c[4], const uint32_t a[4],
                                        const uint32_t b0, const uint32_t b1) {
    asm volatile(
        "mma.sync.aligned.m16n8k16.row.col.f32.f16.f16.f32 "
        "{%0,%1,%2,%3}, {%4,%5,%6,%7}, {%8,%9}, {%0,%1,%2,%3};"
        : "+f"(c[0]), "+f"(c[1]), "+f"(c[2]), "+f"(c[3])
        : "r"(a[0]), "r"(a[1]), "r"(a[2]), "r"(a[3]), "r"(b0), "r"(b1));
}

__device__ __forceinline__ void ldsm_x4(uint32_t& r0, uint32_t& r1,
                                        uint32_t& r2, uint32_t& r3,
                                        uint32_t addr) {
    asm volatile("ldmatrix.sync.aligned.m8n8.x4.shared.b16 {%0,%1,%2,%3}, [%4];"
                 : "=r"(r0), "=r"(r1), "=r"(r2), "=r"(r3) : "r"(addr));
}

// B tile fill: transposed + column-permuted + SW128-swizzled, w2 partials.
// Bs: 128*32 u32 buffer; w2: float[2][128].
__device__ __forceinline__ void fill_b(
    uint32_t* __restrict__ Bs, float* __restrict__ w2,
    const float* __restrict__ w, int j0, int K, int tid, bool full)
{
    int n = tid & 127;            // physical column within tile
    int khalf = tid >> 7;         // k base 0 / 32
    int grp = n >> 4, p = n & 15;
    int tq = p >> 2, s4 = p & 3;
    int L = grp * 16 + (s4 >> 1) * 8 + tq * 2 + (s4 & 1);   // storage row

    const float* wp = w + (j0 + n);
    float s = 0.0f;
    if (full) {
#pragma unroll
        for (int q = 0; q < 4; q++) {
            float f[8];
#pragma unroll
            for (int dd = 0; dd < 8; dd++) {
                int d = khalf * 32 + q * 8 + dd;
                f[dd] = wp[(long)d * K];
                s += f[dd] * f[dd];
            }
            uint4 u = make_uint4(packh2(f[0], f[1]), packh2(f[2], f[3]),
                                 packh2(f[4], f[5]), packh2(f[6], f[7]));
            int word = L * 32 + (((khalf * 4 + q) ^ (L & 7)) << 2);
            *reinterpret_cast<uint4*>(&Bs[word]) = u;
        }
    } else {
        bool inb = (j0 + n < K);
#pragma unroll
        for (int q = 0; q < 4; q++) {
            float f[8];
#pragma unroll
            for (int dd = 0; dd < 8; dd++) {
                int d = khalf * 32 + q * 8 + dd;
                f[dd] = inb ? wp[(long)d * K] : 0.0f;
                s += f[dd] * f[dd];
            }
            uint4 u = make_uint4(packh2(f[0], f[1]), packh2(f[2], f[3]),
                                 packh2(f[4], f[5]), packh2(f[6], f[7]));
            int word = L * 32 + (((khalf * 4 + q) ^ (L & 7)) << 2);
            *reinterpret_cast<uint4*>(&Bs[word]) = u;
        }
    }
    w2[khalf * 128 + n] = s;
}

// ---------------------------------------------------------------------------
// Persistent-strip fused kernel: A tile filled once per chunk; B tiles
// software-pipelined through a 3-deep smem ring (prefetch tile i+1 during
// MMA+epilogue of tile i). CTA 128x128, 256 threads, 8 warps (2m x 4n).
// Dynamic smem (bytes):
//   As   16384            @ 0
//   Bs   3 * 16384        @ 16384
//   x2s  512              @ 65536
//   w2p  3 * 1024         @ 66048     total 69120
// ---------------------------------------------------------------------------
#define SM_AS   0
#define SM_BS   16384
#define SM_X2   65536
#define SM_W2P  66048
#define SM_TOTAL 69120

__global__ __launch_bounds__(NTHREADS, 2) void dist_mma_kernel(
    const float* __restrict__ x, const float* __restrict__ w,
    float* __restrict__ out, int B, int K)
{
    extern __shared__ char smem[];
    uint32_t* As = reinterpret_cast<uint32_t*>(smem + SM_AS);
    float* x2s = reinterpret_cast<float*>(smem + SM_X2);

    const int tid = threadIdx.x;
    const int lane = tid & 31;
    const int wid = tid >> 5;
    const int warp_m = wid >> 2;      // 0..1
    const int warp_n = wid & 3;       // 0..3
    const int m0 = blockIdx.y * TM;

    // ---- chunk of column tiles for this CTA ----
    const int total_jt = (K + TN - 1) / TN;
    const int q = total_jt / NCHUNK;
    const int r = total_jt % NCHUNK;
    const int bx = blockIdx.x;
    const int t_lo = bx * q + min(bx, r);
    const int cnt = q + (bx < r ? 1 : 0);
    if (cnt <= 0) return;

    // ---- A tile fill (ONCE per chunk) + inline x2 via shuffle reduction ----
    {
        const float4* xs = reinterpret_cast<const float4*>(x + (long)m0 * DIM);
#pragma unroll
        for (int i = 0; i < 8; i++) {
            int e = tid + i * NTHREADS;  // float4 index, 0..2047
            int rr = e >> 4;
            int c4 = e & 15;
            float4 v = xs[e];
            float s = v.x * v.x + v.y * v.y + v.z * v.z + v.w * v.w;
            s += __shfl_xor_sync(0xffffffffu, s, 1);
            s += __shfl_xor_sync(0xffffffffu, s, 2);
            s += __shfl_xor_sync(0xffffffffu, s, 4);
            s += __shfl_xor_sync(0xffffffffu, s, 8);
            if (c4 == 0) x2s[rr] = s;
            int word = rr * 32 + ((c4 * 2) ^ ((rr & 7) << 2));
            *reinterpret_cast<uint2*>(&As[word]) =
                make_uint2(packh2(v.x, v.y), packh2(v.z, v.w));
        }
    }

    // ---- prologue: fill ring slot 0 with first B tile ----
    {
        int j0 = t_lo * TN;
        fill_b(reinterpret_cast<uint32_t*>(smem + SM_BS),
               reinterpret_cast<float*>(smem + SM_W2P),
               w, j0, K, tid, j0 + TN <= K);
    }

    // ---- mainloop constants ----
    const int g = lane >> 2;
    const int t = lane & 3;
    uint32_t As_base = (uint32_t)__cvta_generic_to_shared(As);
    uint32_t Bs_base = (uint32_t)__cvta_generic_to_shared(smem + SM_BS);
    const int rowA_loc = lane & 15;
    const int a_klo = lane >> 4;
    const int sxA = rowA_loc & 7;
    const int rowB_loc = (lane & 7) + ((lane >> 4) << 3);
    const int b_klo = (lane >> 3) & 1;
    const int sxB = rowB_loc & 7;
    const uint32_t baseA = As_base + (uint32_t)((warp_m * 64 + rowA_loc) << 7);
    const uint32_t warpB_off = (uint32_t)((warp_n * 32 + rowB_loc) << 7);

    for (int i = 0; i < cnt; i++) {
        const int jt = t_lo + i;
        const int j0 = jt * TN;
        const bool full = (j0 + TN <= K);

        // ---- prefetch next B tile into ring slot (i+1)%3 ----
        if (i + 1 < cnt) {
            int jn = (jt + 1) * TN;
            int slot = (i + 1) % 3;
            fill_b(reinterpret_cast<uint32_t*>(smem + SM_BS + slot * 16384),
                   reinterpret_cast<float*>(smem + SM_W2P + slot * 1024),
                   w, jn, K, tid, jn + TN <= K);
        }

        __syncthreads();

        const int slot = i % 3;
        const uint32_t baseB0 = Bs_base + (uint32_t)(slot * 16384) + warpB_off;
        const uint32_t baseB1 = baseB0 + (16 << 7);
        const float* w2c = reinterpret_cast<const float*>(smem + SM_W2P + slot * 1024);

        // ---- MMA mainloop ----
        float acc[4][4][4];
#pragma unroll
        for (int mt = 0; mt < 4; mt++)
#pragma unroll
            for (int nt = 0; nt < 4; nt++)
#pragma unroll
                for (int qq = 0; qq < 4; qq++) acc[mt][nt][qq] = 0.0f;

#pragma unroll
        for (int ks = 0; ks < 4; ks++) {
            uint32_t colA = (uint32_t)(((2 * ks + a_klo) ^ sxA) << 4);
            uint32_t colB = (uint32_t)(((2 * ks + b_klo) ^ sxB) << 4);

            uint32_t b0[4], b1[4];
            ldsm_x4(b0[0], b0[1], b0[2], b0[3], baseB0 + colB);
            ldsm_x4(b1[0], b1[1], b1[2], b1[3], baseB1 + colB);

#pragma unroll
            for (int mt = 0; mt < 4; mt++) {
                uint32_t a[4];
                ldsm_x4(a[0], a[1], a[2], a[3],
                        baseA + (uint32_t)(mt << 11) + colA);
                mma_f16(acc[mt][0], a, b0[0], b0[1]);
                mma_f16(acc[mt][1], a, b0[2], b0[3]);
                mma_f16(acc[mt][2], a, b1[0], b1[1]);
                mma_f16(acc[mt][3], a, b1[2], b1[3]);
            }
        }

        // ---- Epilogue ----
        float w2v[2][4];
#pragma unroll
        for (int ntp = 0; ntp < 2; ntp++)
#pragma unroll
            for (int qq = 0; qq < 4; qq++) {
                int col = warp_n * 32 + ntp * 16 + 4 * t + qq;
                w2v[ntp][qq] = w2c[col] + w2c[128 + col];
            }

        const int jbase = j0 + warp_n * 32 + 4 * t;

        if (full) {
#pragma unroll
            for (int mt = 0; mt < 4; mt++) {
                int R = warp_m * 64 + mt * 16 + g;
                float x2lo = x2s[R];
                float x2hi = x2s[R + 8];
                float* o0 = out + (long)(m0 + R) * K + jbase;
                float* o1 = out + (long)(m0 + R + 8) * K + jbase;
#pragma unroll
                for (int ntp = 0; ntp < 2; ntp++) {
                    const float* aq0 = acc[mt][2 * ntp + 0];
                    const float* aq1 = acc[mt][2 * ntp + 1];
                    float4 lo, hi;
                    lo.x = dist_val(x2lo + w2v[ntp][0], aq0[0]);
                    lo.y = dist_val(x2lo + w2v[ntp][1], aq0[1]);
                    lo.z = dist_val(x2lo + w2v[ntp][2], aq1[0]);
                    lo.w = dist_val(x2lo + w2v[ntp][3], aq1[1]);
                    hi.x = dist_val(x2hi + w2v[ntp][0], aq0[2]);
                    hi.y = dist_val(x2hi + w2v[ntp][1], aq0[3]);
                    hi.z = dist_val(x2hi + w2v[ntp][2], aq1[2]);
                    hi.w = dist_val(x2hi + w2v[ntp][3], aq1[3]);
                    *reinterpret_cast<float4*>(o0 + ntp * 16) = lo;
                    *reinterpret_cast<float4*>(o1 + ntp * 16) = hi;
                }
            }
        } else {
#pragma unroll
            for (int mt = 0; mt < 4; mt++) {
                int R = warp_m * 64 + mt * 16 + g;
                float x2lo = x2s[R];
                float x2hi = x2s[R + 8];
                long row0 = (long)(m0 + R) * K;
                long row1 = (long)(m0 + R + 8) * K;
                for (int ntp = 0; ntp < 2; ntp++) {
                    const float* aq0 = acc[mt][2 * ntp + 0];
                    const float* aq1 = acc[mt][2 * ntp + 1];
                    for (int qq = 0; qq < 4; qq++) {
                        int j = jbase + ntp * 16 + qq;
                        if (j >= K) continue;
                        float a0 = (qq < 2) ? aq0[qq] : aq1[qq - 2];
                        float a1 = (qq < 2) ? aq0[qq + 2] : aq1[qq];
                        out[row0 + j] = dist_val(x2lo + w2v[ntp][qq], a0);
                        out[row1 + j] = dist_val(x2hi + w2v[ntp][qq], a1);
                    }
                }
            }
        }
    }
}

// ---------------------------------------------------------------------------
// Launch (single kernel)
// ---------------------------------------------------------------------------
extern "C" void kernel_launch(void* const* d_in, const int* in_sizes, int n_in,
                              void* d_out, int out_size) {
    const float* x = (const float*)d_in[0];   // [B, 64]
    const float* w = (const float*)d_in[1];   // [64, K]
    float* out = (float*)d_out;               // [B, K]

    int B = in_sizes[0] / DIM;
    int K = in_sizes[1] / DIM;

    cudaFuncSetAttribute(dist_mma_kernel,
                         cudaFuncAttributeMaxDynamicSharedMemorySize, SM_TOTAL);
    dim3 grid(NCHUNK, (B + TM - 1) / TM);
    dist_mma_kernel<<<grid, NTHREADS, SM_TOTAL>>>(x, w, out, B, K);
}